// round 9
// baseline (speedup 1.0000x reference)
#include <cuda_runtime.h>
#include <cstdint>

#define BATCH  2
#define NPTS   65536
#define KNN    16
#define DCH    32
#define NTILE  64                    // points per block
#define RCH    4                     // channels staged per round
#define NROUND (2 * DCH / RCH)       // 16 rounds covering all 64 channels
#define TILEF  (NTILE * KNN)         // 1024 floats per channel-tile
#define TILEB  (TILEF * 4)           // 4096 bytes per bulk store

__device__ __forceinline__ uint32_t smem_u32(const void* p) {
    uint32_t a;
    asm("{ .reg .u64 t; cvta.to.shared.u64 t, %1; cvt.u32.u64 %0, t; }"
        : "=r"(a) : "l"(p));
    return a;
}

// Tiled kernel with TMA bulk stores. Block owns NTILE points; geometry lives
// in registers. 16 double-buffered rounds: compute 4 channel-tiles into SMEM,
// then one thread bulk-copies four contiguous 4KB regions to GMEM via
// cp.async.bulk (no STG wavefronts; large contiguous DRAM bursts).
__global__ __launch_bounds__(256) void lse_kernel(
    const float* __restrict__ coords,    // (B, N, 3)
    const float* __restrict__ features,  // (B, D, N, 1)
    const int*   __restrict__ idx,       // (B, N, K)
    const float* __restrict__ w,         // (D, 10)
    const float* __restrict__ bias,      // (D,)
    const float* __restrict__ gamma,
    const float* __restrict__ beta,
    const float* __restrict__ mean,
    const float* __restrict__ var,
    float* __restrict__ out)             // (B, 2D, N, K)
{
    __shared__ float4 s_wa[DCH];                              // folded weights
    __shared__ float4 s_wb[DCH];
    __shared__ __align__(128) float s_buf[2][RCH][TILEF];     // 32KB staging

    int t = threadIdx.x;
    if (t < DCH) {
        float sc = gamma[t] * rsqrtf(var[t] + 1e-5f);
        const float* wr = w + t * 10;
        float w0 = wr[0], w1 = wr[1], w2 = wr[2], w3 = wr[3], w4 = wr[4];
        float w5 = wr[5], w6 = wr[6], w7 = wr[7], w8 = wr[8], w9 = wr[9];
        s_wa[t] = make_float4((w0 + w6) * sc, (w1 + w7) * sc, (w2 + w8) * sc,
                              (w3 - w6) * sc);
        s_wb[t] = make_float4((w4 - w7) * sc, (w5 - w8) * sc, w9 * sc,
                              (bias[t] - mean[t]) * sc + beta[t]);
    }

    // thread -> (local point, k-quad)
    int nl = t >> 2;
    int kq = t & 3;
    int b  = blockIdx.x >> 10;                       // NPTS/NTILE = 1024
    int n0 = (blockIdx.x & 1023) * NTILE;
    int n  = n0 + nl;

    const float* cb = coords + (size_t)b * NPTS * 3;
    float cx = cb[(size_t)n * 3 + 0];
    float cy = cb[(size_t)n * 3 + 1];
    float cz = cb[(size_t)n * 3 + 2];

    int4 ii = *reinterpret_cast<const int4*>(
        idx + ((size_t)b * NPTS + (size_t)n) * KNN + kq * 4);

    float nx[4], ny[4], nz[4], dist[4];
#pragma unroll
    for (int j = 0; j < 4; j++) {
        int id = (&ii.x)[j];
        float x = __ldg(cb + (size_t)id * 3 + 0);
        float y = __ldg(cb + (size_t)id * 3 + 1);
        float z = __ldg(cb + (size_t)id * 3 + 2);
        nx[j] = x; ny[j] = y; nz[j] = z;
        float ddx = cx - x, ddy = cy - y, ddz = cz - z;
        dist[j] = sqrtf(ddx * ddx + ddy * ddy + ddz * ddz);
    }
    __syncthreads();   // weights ready

    const uint32_t sbuf0 = smem_u32(&s_buf[0][0][0]);
    const uint32_t sts_off = (uint32_t)t * 16;       // thread t -> byte t*16
    const size_t cstride = (size_t)NPTS * KNN;
    float* out_tile = out + (size_t)b * 2 * DCH * cstride + (size_t)n0 * KNN;
    const float* fb = features + (size_t)b * DCH * NPTS + (size_t)n;

#pragma unroll
    for (int r = 0; r < NROUND; r++) {
        const int rb = r & 1;
        if (r >= 2) {   // buffer rb last committed in round r-2; allow 1 pending
            if (t == 0)
                asm volatile("cp.async.bulk.wait_group.read 1;" ::: "memory");
            __syncthreads();
        }
        const int ch0 = r * RCH;
#pragma unroll
        for (int i = 0; i < RCH; i++) {
            const int ch = ch0 + i;
            float4 rv;
            if (ch < DCH) {
                float4 wa = s_wa[ch];
                float4 wb = s_wb[ch];
                float base = wb.w + wa.x * cx + wa.y * cy + wa.z * cz;
                rv.x = fmaxf(base + wa.w*nx[0] + wb.x*ny[0] + wb.y*nz[0] + wb.z*dist[0], 0.f);
                rv.y = fmaxf(base + wa.w*nx[1] + wb.x*ny[1] + wb.y*nz[1] + wb.z*dist[1], 0.f);
                rv.z = fmaxf(base + wa.w*nx[2] + wb.x*ny[2] + wb.y*nz[2] + wb.z*dist[2], 0.f);
                rv.w = fmaxf(base + wa.w*nx[3] + wb.x*ny[3] + wb.y*nz[3] + wb.z*dist[3], 0.f);
            } else {
                float f = __ldg(fb + (size_t)(ch - DCH) * NPTS);
                rv = make_float4(f, f, f, f);
            }
            *reinterpret_cast<float4*>(
                reinterpret_cast<char*>(&s_buf[rb][i][0]) + sts_off) = rv;
        }
        __syncthreads();
        if (t == 0) {
            asm volatile("fence.proxy.async.shared::cta;" ::: "memory");
#pragma unroll
            for (int i = 0; i < RCH; i++) {
                const int ch = ch0 + i;
                float* dst = out_tile + (size_t)ch * cstride;
                uint32_t src = sbuf0 + (uint32_t)(rb * RCH + i) * TILEB;
                asm volatile(
                    "cp.async.bulk.global.shared::cta.bulk_group [%0], [%1], %2;"
                    :: "l"(dst), "r"(src), "n"(TILEB) : "memory");
            }
            asm volatile("cp.async.bulk.commit_group;" ::: "memory");
        }
    }
    if (t == 0)
        asm volatile("cp.async.bulk.wait_group 0;" ::: "memory");
}

extern "C" void kernel_launch(void* const* d_in, const int* in_sizes, int n_in,
                              void* d_out, int out_size) {
    const float* coords   = (const float*)d_in[0];
    const float* features = (const float*)d_in[1];
    const int*   idx      = (const int*)d_in[2];
    const float* w        = (const float*)d_in[3];
    const float* bias     = (const float*)d_in[4];
    const float* gamma    = (const float*)d_in[5];
    const float* beta     = (const float*)d_in[6];
    const float* mean     = (const float*)d_in[7];
    const float* var      = (const float*)d_in[8];
    float* out = (float*)d_out;

    const int blocks = BATCH * NPTS / NTILE;   // 2048
    lse_kernel<<<blocks, 256>>>(coords, features, idx, w, bias,
                                gamma, beta, mean, var, out);
}

// round 10
// speedup vs baseline: 1.1228x; 1.1228x over previous
#include <cuda_runtime.h>
#include <cuda_bf16.h>

#define BATCH 2
#define NPTS  65536
#define KNN   16
#define DCH   32

// One thread handles (b, n, quad-of-4 k's). All 64 output channels for that
// (n, k-quad) are written as float4 streaming stores (evict-first). 512-thread
// blocks: each block writes 8KB contiguous per channel region.
__global__ __launch_bounds__(512) void lse_kernel(
    const float* __restrict__ coords,    // (B, N, 3)
    const float* __restrict__ features,  // (B, D, N, 1)
    const int*   __restrict__ idx,       // (B, N, K)
    const float* __restrict__ w,         // (D, 10)
    const float* __restrict__ bias,      // (D,)
    const float* __restrict__ gamma,
    const float* __restrict__ beta,
    const float* __restrict__ mean,
    const float* __restrict__ var,
    float* __restrict__ out)             // (B, 2D, N, K)
{
    // Folded per-channel params:
    // dot(w, [ext, nb, ext-nb, dist]) = (w0:3 + w6:9)·ext + (w3:6 - w6:9)·nb + w9*dist
    __shared__ float4 s_wa[DCH];  // we.x, we.y, we.z, wn.x
    __shared__ float4 s_wb[DCH];  // wn.y, wn.z, wd,   bias'
    int t = threadIdx.x;
    if (t < DCH) {
        float sc = gamma[t] * rsqrtf(var[t] + 1e-5f);
        const float* wr = w + t * 10;
        float w0 = wr[0], w1 = wr[1], w2 = wr[2], w3 = wr[3], w4 = wr[4];
        float w5 = wr[5], w6 = wr[6], w7 = wr[7], w8 = wr[8], w9 = wr[9];
        s_wa[t] = make_float4((w0 + w6) * sc, (w1 + w7) * sc, (w2 + w8) * sc,
                              (w3 - w6) * sc);
        s_wb[t] = make_float4((w4 - w7) * sc, (w5 - w8) * sc, w9 * sc,
                              (bias[t] - mean[t]) * sc + beta[t]);
    }
    __syncthreads();

    int gid = blockIdx.x * blockDim.x + t;       // 0 .. B*N*4 - 1
    int kq  = gid & 3;                           // which quad of k
    int n   = (gid >> 2) & (NPTS - 1);
    int b   = gid >> 18;                         // gid / (4*N)

    const float* cb = coords + (size_t)b * NPTS * 3;
    float cx = cb[(size_t)n * 3 + 0];
    float cy = cb[(size_t)n * 3 + 1];
    float cz = cb[(size_t)n * 3 + 2];

    int4 ii = *reinterpret_cast<const int4*>(
        idx + ((size_t)b * NPTS + (size_t)n) * KNN + kq * 4);

    float nx[4], ny[4], nz[4], dist[4];
#pragma unroll
    for (int j = 0; j < 4; j++) {
        int id = (&ii.x)[j];
        float x = __ldg(cb + (size_t)id * 3 + 0);
        float y = __ldg(cb + (size_t)id * 3 + 1);
        float z = __ldg(cb + (size_t)id * 3 + 2);
        nx[j] = x; ny[j] = y; nz[j] = z;
        float ddx = cx - x, ddy = cy - y, ddz = cz - z;
        dist[j] = sqrtf(ddx * ddx + ddy * ddy + ddz * ddz);
    }

    const size_t cstride = (size_t)NPTS * KNN;   // per-channel stride in out
    size_t out_base = (size_t)b * 2 * DCH * cstride + (size_t)n * KNN
                      + (size_t)kq * 4;

    // Computed half: y = relu(conv+BN)
#pragma unroll
    for (int o = 0; o < DCH; o++) {
        float4 wa = s_wa[o];
        float4 wb = s_wb[o];
        float base = wb.w + wa.x * cx + wa.y * cy + wa.z * cz;
        float4 r;
        float* rp = &r.x;
#pragma unroll
        for (int j = 0; j < 4; j++) {
            float v = base + wa.w * nx[j] + wb.x * ny[j] + wb.y * nz[j]
                           + wb.z * dist[j];
            rp[j] = fmaxf(v, 0.0f);
        }
        __stcs(reinterpret_cast<float4*>(out + out_base + (size_t)o * cstride),
               r);
    }

    // Broadcast half: features replicated across K
    const float* fb = features + (size_t)b * DCH * NPTS + (size_t)n;
    size_t fout = out_base + (size_t)DCH * cstride;
#pragma unroll
    for (int c = 0; c < DCH; c++) {
        float f = __ldg(fb + (size_t)c * NPTS);
        __stcs(reinterpret_cast<float4*>(out + fout + (size_t)c * cstride),
               make_float4(f, f, f, f));
    }
}

extern "C" void kernel_launch(void* const* d_in, const int* in_sizes, int n_in,
                              void* d_out, int out_size) {
    const float* coords   = (const float*)d_in[0];
    const float* features = (const float*)d_in[1];
    const int*   idx      = (const int*)d_in[2];
    const float* w        = (const float*)d_in[3];
    const float* bias     = (const float*)d_in[4];
    const float* gamma    = (const float*)d_in[5];
    const float* beta     = (const float*)d_in[6];
    const float* mean     = (const float*)d_in[7];
    const float* var      = (const float*)d_in[8];
    float* out = (float*)d_out;

    const int total   = BATCH * NPTS * 4;   // one thread per (b, n, k-quad)
    const int threads = 512;
    const int blocks  = total / threads;    // 1024
    lse_kernel<<<blocks, threads>>>(coords, features, idx, w, bias,
                                    gamma, beta, mean, var, out);
}